// round 4
// baseline (speedup 1.0000x reference)
#include <cuda_runtime.h>
#include <math.h>
#include <float.h>

#define N_CAND 200000
#define DTXT 768
#define DIMG 1024
#define DC 256
#define KSEL 10
#define NB 148
#define CHUNK 1352   // ceil(200000/148)

// ---- device scratch (no allocations allowed) ----
__device__ float g_sims[N_CAND];
__device__ float g_cv[NB * KSEL];
__device__ int   g_ci[NB * KSEL];
__device__ int   g_idx[KSEL];
__device__ float g_feats[21 * DC];   // post LN+ReLU
__device__ float g_qkv[23 * DC];     // row0=qp, 1..11=kp, 12..22=vp
__device__ float g_out1[DC];
__device__ float g_h1[4 * DC];
__device__ float g_f[DC];
__device__ int   g_bar_cnt = 0;
__device__ volatile int g_bar_gen = 0;

// ---- software grid barrier (all NB CTAs co-resident: 148 blocks x 256 thr) ----
__device__ __forceinline__ void grid_bar() {
    __syncthreads();
    if (threadIdx.x == 0) {
        int gen = g_bar_gen;
        __threadfence();
        if (atomicAdd(&g_bar_cnt, 1) == NB - 1) {
            g_bar_cnt = 0;
            __threadfence();
            g_bar_gen = gen + 1;
        } else {
            while (g_bar_gen == gen) __nanosleep(32);
        }
        __threadfence();
    }
    __syncthreads();
}

// ============================================================
// 1) cosine-sim scan: warp per row-pair, float4, oe=2 CTAs/SM
// ============================================================
__global__ void __launch_bounds__(1024, 2) sim_kernel(const float* __restrict__ query,
                                                      const float* __restrict__ cand) {
    __shared__ float4 qs[DTXT / 4];
    for (int i = threadIdx.x; i < DTXT / 4; i += blockDim.x)
        qs[i] = reinterpret_cast<const float4*>(query)[i];
    __syncthreads();

    int lane = threadIdx.x & 31;
    int gw = (blockIdx.x * blockDim.x + threadIdx.x) >> 5;
    int nw = (gridDim.x * blockDim.x) >> 5;

    for (int row = gw * 2; row < N_CAND; row += 2 * nw) {
        const float4* r0 = reinterpret_cast<const float4*>(cand + (size_t)row * DTXT);
        const float4* r1 = reinterpret_cast<const float4*>(cand + (size_t)(row + 1) * DTXT);
        float4 c0[6], c1[6];
#pragma unroll
        for (int i = 0; i < 6; i++) c0[i] = __ldg(&r0[i * 32 + lane]);
#pragma unroll
        for (int i = 0; i < 6; i++) c1[i] = __ldg(&r1[i * 32 + lane]);

        float d0 = 0.f, s0 = 0.f, d1 = 0.f, s1 = 0.f;
#pragma unroll
        for (int i = 0; i < 6; i++) {
            float4 q = qs[i * 32 + lane];
            d0 += c0[i].x * q.x + c0[i].y * q.y + c0[i].z * q.z + c0[i].w * q.w;
            s0 += c0[i].x * c0[i].x + c0[i].y * c0[i].y + c0[i].z * c0[i].z + c0[i].w * c0[i].w;
            d1 += c1[i].x * q.x + c1[i].y * q.y + c1[i].z * q.z + c1[i].w * q.w;
            s1 += c1[i].x * c1[i].x + c1[i].y * c1[i].y + c1[i].z * c1[i].z + c1[i].w * c1[i].w;
        }
#pragma unroll
        for (int o = 16; o; o >>= 1) {
            d0 += __shfl_xor_sync(0xffffffffu, d0, o);
            s0 += __shfl_xor_sync(0xffffffffu, s0, o);
            d1 += __shfl_xor_sync(0xffffffffu, d1, o);
            s1 += __shfl_xor_sync(0xffffffffu, s1, o);
        }
        if (lane == 0) {
            g_sims[row]     = d0 / fmaxf(sqrtf(s0), 1e-12f);
            g_sims[row + 1] = d1 / fmaxf(sqrtf(s1), 1e-12f);
        }
    }
}

// ---- per-thread register top-10 insert ----
__device__ __forceinline__ void tk_insert(float v, int i, float* tv, int* ti) {
    if (v > tv[KSEL - 1]) {
        int pos = 0;
#pragma unroll
        for (int j = 0; j < KSEL; j++) pos += (tv[j] >= v) ? 1 : 0;
#pragma unroll
        for (int j = KSEL - 2; j >= 0; j--) {
            if (j >= pos) { tv[j + 1] = tv[j]; ti[j + 1] = ti[j]; }
        }
#pragma unroll
        for (int j = 0; j < KSEL; j++) {
            if (j == pos) { tv[j] = v; ti[j] = i; }
        }
    }
}

// 10-round block argmax over 256 threads x KSEL shared candidates
__device__ __forceinline__ void tk_select(float* sv, int* si, float* rv, int* rj,
                                          float* ov, int* oi) {
    int tid = threadIdx.x;
    for (int s = 0; s < KSEL; s++) {
        float best = -FLT_MAX; int bj = tid * KSEL;
#pragma unroll
        for (int j = 0; j < KSEL; j++) {
            float v = sv[tid * KSEL + j];
            if (v > best) { best = v; bj = tid * KSEL + j; }
        }
        rv[tid] = best; rj[tid] = bj;
        __syncthreads();
        for (int off = 128; off; off >>= 1) {
            if (tid < off && rv[tid + off] > rv[tid]) { rv[tid] = rv[tid + off]; rj[tid] = rj[tid + off]; }
            __syncthreads();
        }
        if (tid == 0) { ov[s] = sv[rj[0]]; oi[s] = si[rj[0]]; sv[rj[0]] = -FLT_MAX; }
        __syncthreads();
    }
}

// warp matvec helper: dot of smem x (float4 view) with W row c, nf4 float4 iters
__device__ __forceinline__ float warp_dot(const float4* x4, const float* W, int c,
                                          int nf4, int lane) {
    const float4* w4 = reinterpret_cast<const float4*>(W + (size_t)c * (nf4 * 4));
    float acc = 0.f;
    for (int i = 0; i < nf4 / 32; i++) {
        float4 a = x4[i * 32 + lane];
        float4 w = __ldg(&w4[i * 32 + lane]);
        acc += a.x * w.x + a.y * w.y + a.z * w.z + a.w * w.w;
    }
#pragma unroll
    for (int o = 16; o; o >>= 1) acc += __shfl_xor_sync(0xffffffffu, acc, o);
    return acc;
}

// in-block LN over a 256-wide row in smem; red is 256-float scratch
__device__ __forceinline__ void block_ln(float* row, float* red, float& mean, float& rstd) {
    int t = threadIdx.x;
    red[t] = row[t]; __syncthreads();
    for (int off = 128; off; off >>= 1) { if (t < off) red[t] += red[t + off]; __syncthreads(); }
    float m = red[0] * (1.f / 256.f);
    __syncthreads();
    float d = row[t] - m;
    red[t] = d * d; __syncthreads();
    for (int off = 128; off; off >>= 1) { if (t < off) red[t] += red[t + off]; __syncthreads(); }
    float var = red[0] * (1.f / 256.f);
    __syncthreads();
    mean = m; rstd = rsqrtf(var + 1e-5f);
}

// ============================================================
// 2) everything post-sim in ONE persistent kernel, 148x256
// ============================================================
__global__ void __launch_bounds__(256, 1) rest_kernel(
    const float* __restrict__ query,
    const float* __restrict__ cand_text,
    const float* __restrict__ cand_img,
    const float* __restrict__ proto,
    const float* __restrict__ W_txt, const float* __restrict__ b_txt,
    const float* __restrict__ g_txt, const float* __restrict__ be_txt,
    const float* __restrict__ W_img, const float* __restrict__ b_img,
    const float* __restrict__ g_img, const float* __restrict__ be_img,
    const float* __restrict__ Wq, const float* __restrict__ bq,
    const float* __restrict__ Wk, const float* __restrict__ bk,
    const float* __restrict__ Wv, const float* __restrict__ bv,
    const float* __restrict__ Wo, const float* __restrict__ bo,
    const float* __restrict__ g1, const float* __restrict__ be1,
    const float* __restrict__ W1, const float* __restrict__ b1,
    const float* __restrict__ W2, const float* __restrict__ b2,
    const float* __restrict__ g2, const float* __restrict__ be2,
    float* __restrict__ out) {

    __shared__ __align__(16) float sh[7168];   // 28 KB, aliased per phase
    int t = threadIdx.x, b = blockIdx.x;
    int lane = t & 31, w = t >> 5;

    // ---------- Phase A: per-block top-10 over a chunk ----------
    {
        float* sv = sh;                      // 2560
        int*   si = (int*)(sh + 2560);       // 2560
        float* rv = sh + 5120;               // 256
        int*   rj = (int*)(sh + 5376);       // 256

        float tv[KSEL]; int ti[KSEL];
#pragma unroll
        for (int j = 0; j < KSEL; j++) { tv[j] = -FLT_MAX; ti[j] = -1; }
        int lo = b * CHUNK;
        int hi = min(lo + CHUNK, N_CAND);
        for (int i = lo + t; i < hi; i += 256) tk_insert(g_sims[i], i, tv, ti);
#pragma unroll
        for (int j = 0; j < KSEL; j++) { sv[t * KSEL + j] = tv[j]; si[t * KSEL + j] = ti[j]; }
        __syncthreads();
        tk_select(sv, si, rv, rj, &g_cv[b * KSEL], &g_ci[b * KSEL]);
    }
    grid_bar();

    // ---------- Phase B: block 0 reduces 1480 candidates -> g_idx ----------
    if (b == 0) {
        float* sv = sh;
        int*   si = (int*)(sh + 2560);
        float* rv = sh + 5120;
        int*   rj = (int*)(sh + 5376);
        float* ov = sh + 5632;

        float tv[KSEL]; int ti[KSEL];
#pragma unroll
        for (int j = 0; j < KSEL; j++) { tv[j] = -FLT_MAX; ti[j] = -1; }
        for (int i = t; i < NB * KSEL; i += 256) tk_insert(g_cv[i], g_ci[i], tv, ti);
#pragma unroll
        for (int j = 0; j < KSEL; j++) { sv[t * KSEL + j] = tv[j]; si[t * KSEL + j] = ti[j]; }
        __syncthreads();
        tk_select(sv, si, rv, rj, ov, g_idx);
    }
    grid_bar();

    // ---------- Phase C: proj + LN + ReLU, block-per-row (21 rows) ----------
    if (b < 21) {
        float* xs   = sh;          // up to 1024
        float* zrow = sh + 1024;   // 256
        float* red  = sh + 1280;   // 256

        const float* x; const float* W; const float* bb; int nf;
        const float* gg; const float* be;
        if (b == 0)      { x = query;                                     W = W_txt; bb = b_txt; nf = DTXT; gg = g_txt; be = be_txt; }
        else if (b <= 10){ x = cand_text + (size_t)g_idx[b - 1]  * DTXT;  W = W_txt; bb = b_txt; nf = DTXT; gg = g_txt; be = be_txt; }
        else             { x = cand_img  + (size_t)g_idx[b - 11] * DIMG;  W = W_img; bb = b_img; nf = DIMG; gg = g_img; be = be_img; }

        for (int i = t; i < nf; i += 256) xs[i] = __ldg(&x[i]);
        __syncthreads();

        const float4* x4 = reinterpret_cast<const float4*>(xs);
        int nf4 = nf / 4;
#pragma unroll 4
        for (int j = 0; j < 32; j++) {
            int c = w * 32 + j;
            float acc = warp_dot(x4, W, c, nf4, lane);
            if (lane == 0) zrow[c] = acc + bb[c];
        }
        __syncthreads();

        float m, rstd;
        block_ln(zrow, red, m, rstd);
        float y = (zrow[t] - m) * rstd * gg[t] + be[t];
        g_feats[b * DC + t] = fmaxf(y, 0.f);
    }
    grid_bar();

    // ---------- Phase D: QKV, block-per-row (23 rows) ----------
    if (b < 23) {
        float* xs   = sh;          // 256
        float* zrow = sh + 256;    // not needed globally; write straight out

        const float* x; const float* W; const float* bb;
        if (b == 0)      { x = g_feats;                                    W = Wq; bb = bq; }
        else if (b <= 11){ int n = b - 1;  x = (n == 0) ? proto : (g_feats + n * DC);        W = Wk; bb = bk; }
        else             { int n = b - 12; x = (n == 0) ? proto : (g_feats + (10 + n) * DC); W = Wv; bb = bv; }

        for (int i = t; i < DC; i += 256) xs[i] = x[i];
        __syncthreads();

        const float4* x4 = reinterpret_cast<const float4*>(xs);
#pragma unroll 4
        for (int j = 0; j < 32; j++) {
            int c = w * 32 + j;
            float acc = warp_dot(x4, W, c, DC / 4, lane);
            if (lane == 0) g_qkv[b * DC + c] = acc + bb[c];
        }
        (void)zrow;
    }
    grid_bar();

    // ---------- Phase E: attention + Wo + residual + LN1, block 0 ----------
    if (b == 0) {
        float* qp  = sh;           // 256
        float* kp  = sh + 256;     // 2816
        float* vp  = sh + 3072;    // 2816
        float* at  = sh + 5888;    // 44 (pad to 48)
        float* ctx = sh + 5936;    // 256
        float* sy  = sh + 6192;    // 256
        float* red = sh + 6448;    // 256

        qp[t] = g_qkv[t];
        for (int n = 0; n < 11; n++) {
            kp[n * DC + t] = g_qkv[(1 + n) * DC + t];
            vp[n * DC + t] = g_qkv[(12 + n) * DC + t];
        }
        __syncthreads();

        if (t < 44) {
            int h = t / 11, n = t % 11;
            float s = 0.f;
#pragma unroll
            for (int d = 0; d < 64; d++) s += qp[h * 64 + d] * kp[n * DC + h * 64 + d];
            at[t] = s * 0.125f;
        }
        __syncthreads();
        if (t < 4) {
            float mx = -FLT_MAX;
            for (int n = 0; n < 11; n++) mx = fmaxf(mx, at[t * 11 + n]);
            float sm = 0.f;
            for (int n = 0; n < 11; n++) { float e = expf(at[t * 11 + n] - mx); at[t * 11 + n] = e; sm += e; }
            float inv = 1.f / sm;
            for (int n = 0; n < 11; n++) at[t * 11 + n] *= inv;
        }
        __syncthreads();
        {
            int h = t >> 6;
            float s = 0.f;
            for (int n = 0; n < 11; n++) s += at[h * 11 + n] * vp[n * DC + t];
            ctx[t] = s;
        }
        __syncthreads();

        const float4* c4 = reinterpret_cast<const float4*>(ctx);
#pragma unroll 4
        for (int j = 0; j < 32; j++) {
            int c = w * 32 + j;
            float acc = warp_dot(c4, Wo, c, DC / 4, lane);
            if (lane == 0) sy[c] = acc + bo[c] + proto[c];
        }
        __syncthreads();

        float m, rstd;
        block_ln(sy, red, m, rstd);
        g_out1[t] = (sy[t] - m) * rstd * g1[t] + be1[t];
    }
    grid_bar();

    // ---------- Phase F: FFN1, blocks 0..127, warp-per-output ----------
    if (b < 128) {
        int c = b * 8 + w;
        const float4* x4 = reinterpret_cast<const float4*>(g_out1);
        const float4* w4 = reinterpret_cast<const float4*>(W1 + (size_t)c * DC);
        float acc = 0.f;
#pragma unroll
        for (int i = 0; i < 2; i++) {
            float4 a = __ldg(&x4[i * 32 + lane]);
            float4 ww = __ldg(&w4[i * 32 + lane]);
            acc += a.x * ww.x + a.y * ww.y + a.z * ww.z + a.w * ww.w;
        }
#pragma unroll
        for (int o = 16; o; o >>= 1) acc += __shfl_xor_sync(0xffffffffu, acc, o);
        if (lane == 0) g_h1[c] = fmaxf(acc + b1[c], 0.f);
    }
    grid_bar();

    // ---------- Phase G: FFN2, blocks 0..31, warp-per-output ----------
    if (b < 32) {
        int c = b * 8 + w;
        const float4* x4 = reinterpret_cast<const float4*>(g_h1);
        const float4* w4 = reinterpret_cast<const float4*>(W2 + (size_t)c * (4 * DC));
        float acc = 0.f;
#pragma unroll
        for (int i = 0; i < 8; i++) {
            float4 a = __ldg(&x4[i * 32 + lane]);
            float4 ww = __ldg(&w4[i * 32 + lane]);
            acc += a.x * ww.x + a.y * ww.y + a.z * ww.z + a.w * ww.w;
        }
#pragma unroll
        for (int o = 16; o; o >>= 1) acc += __shfl_xor_sync(0xffffffffu, acc, o);
        if (lane == 0) g_f[c] = acc + b2[c];
    }
    grid_bar();

    // ---------- Phase H: final residual + LN2 + proto, block 0 ----------
    if (b == 0) {
        float* yrow = sh;
        float* red  = sh + 256;
        yrow[t] = g_f[t] + g_out1[t];
        __syncthreads();
        float m, rstd;
        block_ln(yrow, red, m, rstd);
        out[t] = (yrow[t] - m) * rstd * g2[t] + be2[t] + proto[t];
    }
}

// ============================================================
extern "C" void kernel_launch(void* const* d_in, const int* in_sizes, int n_in,
                              void* d_out, int out_size) {
    const float* query     = (const float*)d_in[0];
    const float* cand_text = (const float*)d_in[1];
    const float* cand_img  = (const float*)d_in[2];
    const float* proto     = (const float*)d_in[3];
    const float* W_txt  = (const float*)d_in[4];
    const float* b_txt  = (const float*)d_in[5];
    const float* g_txt  = (const float*)d_in[6];
    const float* be_txt = (const float*)d_in[7];
    const float* W_img  = (const float*)d_in[8];
    const float* b_img  = (const float*)d_in[9];
    const float* g_img  = (const float*)d_in[10];
    const float* be_img = (const float*)d_in[11];
    const float* Wq = (const float*)d_in[12];
    const float* bq = (const float*)d_in[13];
    const float* Wk = (const float*)d_in[14];
    const float* bk = (const float*)d_in[15];
    const float* Wv = (const float*)d_in[16];
    const float* bv = (const float*)d_in[17];
    const float* Wo = (const float*)d_in[18];
    const float* bo = (const float*)d_in[19];
    const float* g1  = (const float*)d_in[20];
    const float* be1 = (const float*)d_in[21];
    const float* W1 = (const float*)d_in[22];
    const float* b1 = (const float*)d_in[23];
    const float* W2 = (const float*)d_in[24];
    const float* b2 = (const float*)d_in[25];
    const float* g2  = (const float*)d_in[26];
    const float* be2 = (const float*)d_in[27];
    float* out = (float*)d_out;

    sim_kernel<<<296, 1024>>>(query, cand_text);
    rest_kernel<<<NB, 256>>>(query, cand_text, cand_img, proto,
                             W_txt, b_txt, g_txt, be_txt,
                             W_img, b_img, g_img, be_img,
                             Wq, bq, Wk, bk, Wv, bv, Wo, bo,
                             g1, be1, W1, b1, W2, b2, g2, be2, out);
}

// round 5
// speedup vs baseline: 1.2526x; 1.2526x over previous
#include <cuda_runtime.h>
#include <math.h>
#include <float.h>

#define N_CAND 200000
#define DTXT 768
#define DIMG 1024
#define DC 256
#define KSEL 10
#define SIM_BLOCKS 296

// ---- device scratch (no allocations allowed) ----
__device__ float g_cv[SIM_BLOCKS * KSEL];
__device__ int   g_ci[SIM_BLOCKS * KSEL];
__device__ int   g_idx[KSEL];
__device__ float g_feats[21 * DC];   // post LN+ReLU
__device__ float g_qkv[23 * DC];     // row0=qp, 1..11=kp, 12..22=vp
__device__ float g_out1[DC];
__device__ float g_h1[4 * DC];
__device__ float g_f[DC];

// ---- per-thread register top-10 insert (list sorted descending) ----
__device__ __forceinline__ void tk_insert(float v, int i, float* tv, int* ti) {
    if (v > tv[KSEL - 1]) {
        int pos = 0;
#pragma unroll
        for (int j = 0; j < KSEL; j++) pos += (tv[j] >= v) ? 1 : 0;
#pragma unroll
        for (int j = KSEL - 2; j >= 0; j--) {
            if (j >= pos) { tv[j + 1] = tv[j]; ti[j + 1] = ti[j]; }
        }
#pragma unroll
        for (int j = 0; j < KSEL; j++) {
            if (j == pos) { tv[j] = v; ti[j] = i; }
        }
    }
}

// ============================================================
// 1) cosine-sim scan + fused per-block top-10
//    warp per row, __ldcs streaming loads (protect L2 for weights)
// ============================================================
__global__ void __launch_bounds__(1024, 1) sim_kernel(const float* __restrict__ query,
                                                      const float* __restrict__ cand) {
    __shared__ float4 qs[DTXT / 4];
    __shared__ float wtv[32 * KSEL];
    __shared__ int   wti[32 * KSEL];

    for (int i = threadIdx.x; i < DTXT / 4; i += blockDim.x)
        qs[i] = reinterpret_cast<const float4*>(query)[i];
    __syncthreads();

    int lane = threadIdx.x & 31;
    int wid = threadIdx.x >> 5;
    int gw = (blockIdx.x * blockDim.x + threadIdx.x) >> 5;
    int nw = (gridDim.x * blockDim.x) >> 5;   // 9472 warps

    float tv[KSEL]; int ti[KSEL];
#pragma unroll
    for (int j = 0; j < KSEL; j++) { tv[j] = -FLT_MAX; ti[j] = -1; }

    for (int row = gw; row < N_CAND; row += nw) {
        const float4* rp = reinterpret_cast<const float4*>(cand + (size_t)row * DTXT);
        float4 c[6];
#pragma unroll
        for (int i = 0; i < 6; i++) c[i] = __ldcs(&rp[i * 32 + lane]);

        float dot = 0.f, ss = 0.f;
#pragma unroll
        for (int i = 0; i < 6; i++) {
            float4 q = qs[i * 32 + lane];
            dot += c[i].x * q.x + c[i].y * q.y + c[i].z * q.z + c[i].w * q.w;
            ss  += c[i].x * c[i].x + c[i].y * c[i].y + c[i].z * c[i].z + c[i].w * c[i].w;
        }
#pragma unroll
        for (int o = 16; o; o >>= 1) {
            dot += __shfl_xor_sync(0xffffffffu, dot, o);
            ss  += __shfl_xor_sync(0xffffffffu, ss,  o);
        }
        if (lane == 0) {
            float s = dot / fmaxf(sqrtf(ss), 1e-12f);
            tk_insert(s, row, tv, ti);
        }
    }

    // per-warp top-10 (sorted desc) -> smem
    if (lane == 0) {
#pragma unroll
        for (int j = 0; j < KSEL; j++) { wtv[wid * KSEL + j] = tv[j]; wti[wid * KSEL + j] = ti[j]; }
    }
    __syncthreads();

    // warp 0: 32-way merge of sorted lists, select block top-10
    if (wid == 0) {
        int ptr = 0;
        for (int s = 0; s < KSEL; s++) {
            float v = (ptr < KSEL) ? wtv[lane * KSEL + ptr] : -FLT_MAX;
            float bv = v; int bl = lane;
#pragma unroll
            for (int o = 16; o; o >>= 1) {
                float ov = __shfl_xor_sync(0xffffffffu, bv, o);
                int   ol = __shfl_xor_sync(0xffffffffu, bl, o);
                if (ov > bv) { bv = ov; bl = ol; }
            }
            if (lane == bl) {
                g_cv[blockIdx.x * KSEL + s] = v;
                g_ci[blockIdx.x * KSEL + s] = wti[lane * KSEL + ptr];
                ptr++;
            }
        }
    }
}

// ============================================================
// 2) top-10 final: reduce 2960 candidates -> g_idx (1 block)
// ============================================================
__global__ void topkB_kernel() {
    __shared__ float sv[256 * KSEL];
    __shared__ int   si[256 * KSEL];
    __shared__ float rv[256];
    __shared__ int   rj[256];
    int tid = threadIdx.x;

    float tv[KSEL]; int ti[KSEL];
#pragma unroll
    for (int j = 0; j < KSEL; j++) { tv[j] = -FLT_MAX; ti[j] = -1; }
    for (int i = tid; i < SIM_BLOCKS * KSEL; i += 256)
        tk_insert(g_cv[i], g_ci[i], tv, ti);
#pragma unroll
    for (int j = 0; j < KSEL; j++) { sv[tid * KSEL + j] = tv[j]; si[tid * KSEL + j] = ti[j]; }
    __syncthreads();

    for (int s = 0; s < KSEL; s++) {
        float best = -FLT_MAX; int bj = tid * KSEL;
#pragma unroll
        for (int j = 0; j < KSEL; j++) {
            float v = sv[tid * KSEL + j];
            if (v > best) { best = v; bj = tid * KSEL + j; }
        }
        rv[tid] = best; rj[tid] = bj;
        __syncthreads();
        for (int off = 128; off; off >>= 1) {
            if (tid < off && rv[tid + off] > rv[tid]) { rv[tid] = rv[tid + off]; rj[tid] = rj[tid + off]; }
            __syncthreads();
        }
        if (tid == 0) { g_idx[s] = si[rj[0]]; sv[rj[0]] = -FLT_MAX; }
        __syncthreads();
    }
}

// ============================================================
// 3) proj + LN + ReLU fused, block-per-row, 21 blocks x 1024
// ============================================================
__global__ void __launch_bounds__(1024, 1) projln_kernel(
    const float* __restrict__ query,
    const float* __restrict__ cand_text,
    const float* __restrict__ cand_img,
    const float* __restrict__ W_txt, const float* __restrict__ b_txt,
    const float* __restrict__ g_txt, const float* __restrict__ be_txt,
    const float* __restrict__ W_img, const float* __restrict__ b_img,
    const float* __restrict__ g_img, const float* __restrict__ be_img) {

    __shared__ __align__(16) float xs[DIMG];
    __shared__ float zrow[DC];
    __shared__ float red[DC];
    int t = threadIdx.x, b = blockIdx.x;
    int lane = t & 31, w = t >> 5;

    const float* x; const float* W; const float* bb; int nf;
    const float* gg; const float* be;
    if (b == 0)      { x = query;                                     W = W_txt; bb = b_txt; nf = DTXT; gg = g_txt; be = be_txt; }
    else if (b <= 10){ x = cand_text + (size_t)g_idx[b - 1]  * DTXT;  W = W_txt; bb = b_txt; nf = DTXT; gg = g_txt; be = be_txt; }
    else             { x = cand_img  + (size_t)g_idx[b - 11] * DIMG;  W = W_img; bb = b_img; nf = DIMG; gg = g_img; be = be_img; }

    for (int i = t; i < nf; i += 1024) xs[i] = __ldg(&x[i]);
    __syncthreads();

    const float4* x4 = reinterpret_cast<const float4*>(xs);
    int nf4 = nf / 4;
    // 32 warps x 8 outputs each
#pragma unroll
    for (int j = 0; j < 8; j++) {
        int c = w * 8 + j;
        const float4* w4 = reinterpret_cast<const float4*>(W + (size_t)c * nf);
        float acc = 0.f;
        for (int i = 0; i < nf4 / 32; i++) {
            float4 a = x4[i * 32 + lane];
            float4 ww = __ldg(&w4[i * 32 + lane]);
            acc += a.x * ww.x + a.y * ww.y + a.z * ww.z + a.w * ww.w;
        }
#pragma unroll
        for (int o = 16; o; o >>= 1) acc += __shfl_xor_sync(0xffffffffu, acc, o);
        if (lane == 0) zrow[c] = acc + bb[c];
    }
    __syncthreads();

    // LN + ReLU over zrow[256] (threads >=256 only hit the syncs)
    if (t < DC) red[t] = zrow[t];
    __syncthreads();
    for (int off = 128; off; off >>= 1) { if (t < off) red[t] += red[t + off]; __syncthreads(); }
    float m = red[0] * (1.f / 256.f);
    __syncthreads();
    if (t < DC) { float d = zrow[t] - m; red[t] = d * d; }
    __syncthreads();
    for (int off = 128; off; off >>= 1) { if (t < off) red[t] += red[t + off]; __syncthreads(); }
    float var = red[0] * (1.f / 256.f);
    if (t < DC) {
        float y = (zrow[t] - m) * rsqrtf(var + 1e-5f) * gg[t] + be[t];
        g_feats[b * DC + t] = fmaxf(y, 0.f);
    }
}

// ============================================================
// 4) QKV matvecs: warp per output (23 rows x 256)
// ============================================================
__global__ void qkv_kernel(const float* __restrict__ proto,
                           const float* __restrict__ Wq, const float* __restrict__ bq,
                           const float* __restrict__ Wk, const float* __restrict__ bk,
                           const float* __restrict__ Wv, const float* __restrict__ bv) {
    int gw = (blockIdx.x * blockDim.x + threadIdx.x) >> 5;
    int lane = threadIdx.x & 31;
    int r = gw >> 8;
    int c = gw & 255;
    if (r >= 23) return;

    const float* x; const float* W; const float* b;
    if (r == 0)      { x = g_feats;                                    W = Wq; b = bq; }
    else if (r <= 11){ int n = r - 1;  x = (n == 0) ? proto : (g_feats + n * DC);        W = Wk; b = bk; }
    else             { int n = r - 12; x = (n == 0) ? proto : (g_feats + (10 + n) * DC); W = Wv; b = bv; }

    const float4* x4 = reinterpret_cast<const float4*>(x);
    const float4* w4 = reinterpret_cast<const float4*>(W + (size_t)c * DC);
    float acc = 0.f;
#pragma unroll
    for (int i = 0; i < 2; i++) {
        float4 a = __ldg(&x4[i * 32 + lane]);
        float4 w = __ldg(&w4[i * 32 + lane]);
        acc += a.x * w.x + a.y * w.y + a.z * w.z + a.w * w.w;
    }
#pragma unroll
    for (int o = 16; o; o >>= 1) acc += __shfl_xor_sync(0xffffffffu, acc, o);
    if (lane == 0) g_qkv[r * DC + c] = acc + b[c];
}

// ============================================================
// 5) attention + Wo (coalesced warp-per-output) + residual + LN1
// ============================================================
__global__ void __launch_bounds__(1024, 1) attn_kernel(const float* __restrict__ proto,
                            const float* __restrict__ Wo, const float* __restrict__ bo,
                            const float* __restrict__ g1, const float* __restrict__ be1) {
    __shared__ float qp[DC], kp[11 * DC], vp[11 * DC], at[44], ctx[DC], sy[DC], red[256];
    int t = threadIdx.x;
    int lane = t & 31, w = t >> 5;

    for (int i = t; i < DC; i += 1024) qp[i] = g_qkv[i];
    for (int i = t; i < 11 * DC; i += 1024) {
        kp[i] = g_qkv[DC + i];
        vp[i] = g_qkv[12 * DC + i];
    }
    __syncthreads();

    if (t < 44) {
        int h = t / 11, n = t % 11;
        float s = 0.f;
#pragma unroll
        for (int d = 0; d < 64; d++) s += qp[h * 64 + d] * kp[n * DC + h * 64 + d];
        at[t] = s * 0.125f;
    }
    __syncthreads();
    if (t < 4) {
        float mx = -FLT_MAX;
        for (int n = 0; n < 11; n++) mx = fmaxf(mx, at[t * 11 + n]);
        float sm = 0.f;
        for (int n = 0; n < 11; n++) { float e = expf(at[t * 11 + n] - mx); at[t * 11 + n] = e; sm += e; }
        float inv = 1.f / sm;
        for (int n = 0; n < 11; n++) at[t * 11 + n] *= inv;
    }
    __syncthreads();
    if (t < DC) {
        int h = t >> 6;
        float s = 0.f;
        for (int n = 0; n < 11; n++) s += at[h * 11 + n] * vp[n * DC + t];
        ctx[t] = s;
    }
    __syncthreads();

    const float4* c4 = reinterpret_cast<const float4*>(ctx);
#pragma unroll
    for (int j = 0; j < 8; j++) {
        int c = w * 8 + j;
        const float4* w4 = reinterpret_cast<const float4*>(Wo + (size_t)c * DC);
        float acc = 0.f;
#pragma unroll
        for (int i = 0; i < 2; i++) {
            float4 a = c4[i * 32 + lane];
            float4 ww = __ldg(&w4[i * 32 + lane]);
            acc += a.x * ww.x + a.y * ww.y + a.z * ww.z + a.w * ww.w;
        }
#pragma unroll
        for (int o = 16; o; o >>= 1) acc += __shfl_xor_sync(0xffffffffu, acc, o);
        if (lane == 0) sy[c] = acc + bo[c] + proto[c];
    }
    __syncthreads();

    if (t < 256) red[t] = sy[t];
    __syncthreads();
    for (int off = 128; off; off >>= 1) { if (t < off) red[t] += red[t + off]; __syncthreads(); }
    float m = red[0] * (1.f / 256.f);
    __syncthreads();
    if (t < 256) { float dd = sy[t] - m; red[t] = dd * dd; }
    __syncthreads();
    for (int off = 128; off; off >>= 1) { if (t < off) red[t] += red[t + off]; __syncthreads(); }
    float var = red[0] * (1.f / 256.f);
    if (t < 256) g_out1[t] = (sy[t] - m) * rsqrtf(var + 1e-5f) * g1[t] + be1[t];
}

// ============================================================
// 6) FFN layer 1: warp per output (1024 outputs, dot-256)
// ============================================================
__global__ void __launch_bounds__(1024, 1) ffn1_kernel(const float* __restrict__ W1,
                                                       const float* __restrict__ b1) {
    int gw = (blockIdx.x * blockDim.x + threadIdx.x) >> 5;
    int lane = threadIdx.x & 31;
    const float4* x4 = reinterpret_cast<const float4*>(g_out1);
    const float4* w4 = reinterpret_cast<const float4*>(W1 + (size_t)gw * DC);
    float acc = 0.f;
#pragma unroll
    for (int i = 0; i < 2; i++) {
        float4 a = __ldg(&x4[i * 32 + lane]);
        float4 w = __ldg(&w4[i * 32 + lane]);
        acc += a.x * w.x + a.y * w.y + a.z * w.z + a.w * w.w;
    }
#pragma unroll
    for (int o = 16; o; o >>= 1) acc += __shfl_xor_sync(0xffffffffu, acc, o);
    if (lane == 0) g_h1[gw] = fmaxf(acc + b1[gw], 0.f);
}

// ============================================================
// 7) FFN layer 2: warp per output (256 outputs, dot-1024)
// ============================================================
__global__ void __launch_bounds__(1024, 1) ffn2_kernel(const float* __restrict__ W2,
                                                       const float* __restrict__ b2) {
    int gw = (blockIdx.x * blockDim.x + threadIdx.x) >> 5;
    int lane = threadIdx.x & 31;
    const float4* x4 = reinterpret_cast<const float4*>(g_h1);
    const float4* w4 = reinterpret_cast<const float4*>(W2 + (size_t)gw * (4 * DC));
    float acc = 0.f;
#pragma unroll
    for (int i = 0; i < 8; i++) {
        float4 a = __ldg(&x4[i * 32 + lane]);
        float4 w = __ldg(&w4[i * 32 + lane]);
        acc += a.x * w.x + a.y * w.y + a.z * w.z + a.w * w.w;
    }
#pragma unroll
    for (int o = 16; o; o >>= 1) acc += __shfl_xor_sync(0xffffffffu, acc, o);
    if (lane == 0) g_f[gw] = acc + b2[gw];
}

// ============================================================
// 8) final residual + LN2 + proto add -> d_out
// ============================================================
__global__ void ffn3_kernel(const float* __restrict__ proto,
                            const float* __restrict__ g2, const float* __restrict__ be2,
                            float* __restrict__ out) {
    __shared__ float red[256];
    int t = threadIdx.x;
    float y = g_f[t] + g_out1[t];
    red[t] = y; __syncthreads();
    for (int off = 128; off; off >>= 1) { if (t < off) red[t] += red[t + off]; __syncthreads(); }
    float m = red[0] * (1.f / 256.f);
    __syncthreads();
    float dd = y - m;
    red[t] = dd * dd; __syncthreads();
    for (int off = 128; off; off >>= 1) { if (t < off) red[t] += red[t + off]; __syncthreads(); }
    float var = red[0] * (1.f / 256.f);
    out[t] = dd * rsqrtf(var + 1e-5f) * g2[t] + be2[t] + proto[t];
}

// ============================================================
extern "C" void kernel_launch(void* const* d_in, const int* in_sizes, int n_in,
                              void* d_out, int out_size) {
    const float* query     = (const float*)d_in[0];
    const float* cand_text = (const float*)d_in[1];
    const float* cand_img  = (const float*)d_in[2];
    const float* proto     = (const float*)d_in[3];
    const float* W_txt  = (const float*)d_in[4];
    const float* b_txt  = (const float*)d_in[5];
    const float* g_txt  = (const float*)d_in[6];
    const float* be_txt = (const float*)d_in[7];
    const float* W_img  = (const float*)d_in[8];
    const float* b_img  = (const float*)d_in[9];
    const float* g_img  = (const float*)d_in[10];
    const float* be_img = (const float*)d_in[11];
    const float* Wq = (const float*)d_in[12];
    const float* bq = (const float*)d_in[13];
    const float* Wk = (const float*)d_in[14];
    const float* bk = (const float*)d_in[15];
    const float* Wv = (const float*)d_in[16];
    const float* bv = (const float*)d_in[17];
    const float* Wo = (const float*)d_in[18];
    const float* bo = (const float*)d_in[19];
    const float* g1  = (const float*)d_in[20];
    const float* be1 = (const float*)d_in[21];
    const float* W1 = (const float*)d_in[22];
    const float* b1 = (const float*)d_in[23];
    const float* W2 = (const float*)d_in[24];
    const float* b2 = (const float*)d_in[25];
    const float* g2  = (const float*)d_in[26];
    const float* be2 = (const float*)d_in[27];
    float* out = (float*)d_out;

    sim_kernel<<<SIM_BLOCKS, 1024>>>(query, cand_text);
    topkB_kernel<<<1, 256>>>();
    projln_kernel<<<21, 1024>>>(query, cand_text, cand_img,
                                W_txt, b_txt, g_txt, be_txt,
                                W_img, b_img, g_img, be_img);
    qkv_kernel<<<736, 256>>>(proto, Wq, bq, Wk, bk, Wv, bv);
    attn_kernel<<<1, 1024>>>(proto, Wo, bo, g1, be1);
    ffn1_kernel<<<32, 1024>>>(W1, b1);
    ffn2_kernel<<<8, 1024>>>(W2, b2);
    ffn3_kernel<<<1, 256>>>(proto, g2, be2, out);
}